// round 6
// baseline (speedup 1.0000x reference)
#include <cuda_runtime.h>
#include <cstdint>

// out[100000,128] = x[100000,128] @ (Wc+Wn)[128,128] + b[128]
// (gamma/segment-sum in the reference is dead code; edge_index unused)
//
// tf32 mma.sync (m16n8k8). Persistent CTAs (2/SM): W tile resident in smem,
// x streamed via cp.async double-buffered K=32 chunks, pipelined ACROSS tiles.
//
// Inputs: d_in[0]=x f32 [100000,128], d_in[1]=edge_index i64 (UNUSED),
//         d_in[2]=Wc f32 [128,128], d_in[3]=Wn f32 [128,128], d_in[4]=b f32 [128]

#define D 128
#define TILE_M 128
#define KC 32
#define CS 36                     // row stride in floats -> conflict-free frag reads
#define XBUF (TILE_M * CS)        // 4608 floats per buffer/chunk

// W^T, tf32(RNA)-rounded: g_Wt[n*128 + k] = tf32(Wc[k][n] + Wn[k][n])
__device__ float g_Wt[D * D];

__device__ __forceinline__ float to_tf32(float f) {
    float r;
    asm("cvt.rna.tf32.f32 %0, %1;" : "=f"(r) : "f"(f));
    return r;
}

__global__ void prep_w_kernel(const float* __restrict__ Wc,
                              const float* __restrict__ Wn) {
    int i = blockIdx.x * blockDim.x + threadIdx.x;
    if (i >= D * D) return;
    int n = i >> 7, k = i & 127;
    g_Wt[n * D + k] = to_tf32(Wc[k * D + n] + Wn[k * D + n]);
}

#define MMA_TF32(c, a0, a1, a2, a3, b0, b1)                                   \
    asm volatile(                                                             \
        "mma.sync.aligned.m16n8k8.row.col.f32.tf32.tf32.f32 "                 \
        "{%0,%1,%2,%3}, {%4,%5,%6,%7}, {%8,%9}, {%0,%1,%2,%3};"               \
        : "+f"((c)[0]), "+f"((c)[1]), "+f"((c)[2]), "+f"((c)[3])              \
        : "r"(a0), "r"(a1), "r"(a2), "r"(a3), "r"(b0), "r"(b1))

__device__ __forceinline__ void cp_async16(uint32_t dst, const void* src, int valid) {
    asm volatile("cp.async.cg.shared.global [%0], [%1], 16, %2;"
                 :: "r"(dst), "l"(src), "r"(valid ? 16 : 0));
}

__global__ __launch_bounds__(256, 2)
void gemm_tf32_kernel(const float* __restrict__ x,
                      const float* __restrict__ bias,
                      float* __restrict__ out, int nrows, int ntiles) {
    extern __shared__ float sm[];
    float* xs = sm;                  // [2][4608]  x double buffer
    float* ws = sm + 2 * XBUF;       // [4][4608]  full W tile, chunk layout

    const int tid = threadIdx.x;
    const int lane = tid & 31;
    const int wid = tid >> 5;
    const int g = lane >> 2;
    const int t4 = lane & 3;
    const int wm = wid >> 1;         // 0..3 (32 rows)
    const int wn = wid & 1;          // 0..1 (64 cols)

    const int lr = tid >> 3;         // 0..31
    const int lk = (tid & 7) << 2;   // 0,4,...,28

    const uint32_t xs_b = (uint32_t)__cvta_generic_to_shared(xs);
    const uint32_t ws_b = (uint32_t)__cvta_generic_to_shared(ws);

    // ---- W tile: one-time load into smem (chunk layout), group 0 ----
    {
#pragma unroll
        for (int it = 0; it < 16; it++) {
            int idx = tid + 256 * it;        // float4 index, 0..4095
            int n = idx >> 5;                // row 0..127
            int j4 = (idx & 31) << 2;        // k 0..124
            int c = j4 >> 5, kin = j4 & 31;
            cp_async16(ws_b + (uint32_t)(c * XBUF + n * CS + kin) * 4,
                       g_Wt + (size_t)n * D + j4, 1);
        }
        asm volatile("cp.async.commit_group;" ::: "memory");
    }

    auto load_x_chunk = [&](int row0, int k0, int buf) {
        uint32_t xd = xs_b + (uint32_t)(buf * XBUF) * 4;
#pragma unroll
        for (int it = 0; it < 4; it++) {
            int r = lr + 32 * it;
            int grow = row0 + r;
            cp_async16(xd + (uint32_t)(r * CS + lk) * 4,
                       x + (size_t)grow * D + k0 + lk, grow < nrows);
        }
        asm volatile("cp.async.commit_group;" ::: "memory");
    };

    // prologue: chunk 0 of first tile
    const int tile0 = blockIdx.x;
    if (tile0 < ntiles) load_x_chunk(tile0 * TILE_M, 0, 0);
    else asm volatile("cp.async.commit_group;" ::: "memory");

    int q = 0;  // global chunk counter (buffer parity)
    for (int t = tile0; t < ntiles; t += gridDim.x) {
        const int row0 = t * TILE_M;

        float acc[2][8][4];
#pragma unroll
        for (int i = 0; i < 2; i++)
#pragma unroll
            for (int j = 0; j < 8; j++)
#pragma unroll
                for (int p = 0; p < 4; p++) acc[i][j][p] = 0.0f;

#pragma unroll
        for (int c = 0; c < 4; c++, q++) {
            // issue next chunk (next K-chunk, or next tile's chunk 0)
            if (c < 3) {
                load_x_chunk(row0, (c + 1) * KC, (q + 1) & 1);
            } else {
                int nt = t + gridDim.x;
                if (nt < ntiles) load_x_chunk(nt * TILE_M, 0, (q + 1) & 1);
                else asm volatile("cp.async.commit_group;" ::: "memory");
            }
            asm volatile("cp.async.wait_group 1;" ::: "memory");
            __syncthreads();

            const uint32_t* xa =
                (const uint32_t*)(xs + (q & 1) * XBUF + (wm * 32 + g) * CS + t4);
            const uint32_t* wb =
                (const uint32_t*)(ws + c * XBUF + (wn * 64 + g) * CS + t4);

#pragma unroll
            for (int s = 0; s < 4; s++) {
                const int k8 = 8 * s;
                uint32_t a[2][4];
#pragma unroll
                for (int i = 0; i < 2; i++) {
                    a[i][0] = xa[(16 * i) * CS + k8];
                    a[i][1] = xa[(16 * i + 8) * CS + k8];
                    a[i][2] = xa[(16 * i) * CS + k8 + 4];
                    a[i][3] = xa[(16 * i + 8) * CS + k8 + 4];
                }
                uint32_t b[8][2];
#pragma unroll
                for (int j = 0; j < 8; j++) {
                    b[j][0] = wb[j * 8 * CS + k8];
                    b[j][1] = wb[j * 8 * CS + k8 + 4];
                }
#pragma unroll
                for (int i = 0; i < 2; i++)
#pragma unroll
                    for (int j = 0; j < 8; j++)
                        MMA_TF32(acc[i][j], a[i][0], a[i][1], a[i][2], a[i][3],
                                 b[j][0], b[j][1]);
            }
            __syncthreads();
        }

        // ---- epilogue: bias + store directly from accumulators ----
#pragma unroll
        for (int j = 0; j < 8; j++) {
            int col = wn * 64 + 8 * j + 2 * t4;
            float b0 = __ldg(bias + col), b1 = __ldg(bias + col + 1);
#pragma unroll
            for (int i = 0; i < 2; i++) {
                int r_lo = row0 + wm * 32 + 16 * i + g;
                int r_hi = r_lo + 8;
                if (r_lo < nrows) {
                    float2 v = make_float2(acc[i][j][0] + b0, acc[i][j][1] + b1);
                    *(float2*)(out + (size_t)r_lo * D + col) = v;
                }
                if (r_hi < nrows) {
                    float2 v = make_float2(acc[i][j][2] + b0, acc[i][j][3] + b1);
                    *(float2*)(out + (size_t)r_hi * D + col) = v;
                }
            }
        }
    }
}

extern "C" void kernel_launch(void* const* d_in, const int* in_sizes, int n_in,
                              void* d_out, int out_size) {
    const float* x    = (const float*)d_in[0];
    const float* Wc   = (const float*)d_in[2];
    const float* Wn   = (const float*)d_in[3];
    const float* bias = (const float*)d_in[4];
    float* out = (float*)d_out;

    const int nrows = in_sizes[0] / D;                 // 100000
    const int ntiles = (nrows + TILE_M - 1) / TILE_M;  // 782

    prep_w_kernel<<<(D * D + 255) / 256, 256>>>(Wc, Wn);

    const int smem_bytes = (2 * XBUF + 4 * XBUF) * 4;  // 110,592 B
    cudaFuncSetAttribute(gemm_tf32_kernel,
                         cudaFuncAttributeMaxDynamicSharedMemorySize, smem_bytes);

    int grid = 296;                                    // ~2 CTAs/SM, persistent
    if (grid > ntiles) grid = ntiles;
    gemm_tf32_kernel<<<grid, 256, smem_bytes>>>(x, bias, out, nrows, ntiles);
}

// round 7
// speedup vs baseline: 1.0339x; 1.0339x over previous
#include <cuda_runtime.h>
#include <cstdint>

// out[100000,128] = x[100000,128] @ (Wc+Wn)[128,128] + b[128]
// (gamma/segment-sum in the reference is dead code; edge_index unused)
//
// tf32 mma.sync (m16n8k8), cp.async K=32 chunks, ONE sync/chunk,
// W k-pair-permuted so B fragments load as float2 (LDS.64).
//
// Inputs: d_in[0]=x f32 [100000,128], d_in[1]=edge_index i64 (UNUSED),
//         d_in[2]=Wc f32 [128,128], d_in[3]=Wn f32 [128,128], d_in[4]=b f32 [128]

#define D 128
#define TILE_M 128
#define KC 32
#define CS 36                    // row stride (floats): conflict-free LDS.32 pattern
#define XBUF (TILE_M * CS)       // 4608 floats

// W image: [chunk c][n][kin 0..31], kin permuted within each 8-group so that
// (k8+t4, k8+t4+4) are adjacent: pos(u) = 2*(u&3) + (u>>2).
__device__ float g_Wt[D * D];

__device__ __forceinline__ float to_tf32(float f) {
    float r;
    asm("cvt.rna.tf32.f32 %0, %1;" : "=f"(r) : "f"(f));
    return r;
}

__global__ void prep_w_kernel(const float* __restrict__ Wc,
                              const float* __restrict__ Wn) {
    int i = blockIdx.x * blockDim.x + threadIdx.x;   // image index
    if (i >= D * D) return;
    int c = i >> 12, n = (i >> 5) & 127, kin = i & 31;
    int s = kin >> 3, p = kin & 7;
    int u = ((p & 1) << 2) | (p >> 1);               // inverse of pos()
    int k = c * 32 + s * 8 + u;
    g_Wt[i] = to_tf32(Wc[k * D + n] + Wn[k * D + n]);
}

#define MMA_TF32(c, a0, a1, a2, a3, b0, b1)                                   \
    asm volatile(                                                             \
        "mma.sync.aligned.m16n8k8.row.col.f32.tf32.tf32.f32 "                 \
        "{%0,%1,%2,%3}, {%4,%5,%6,%7}, {%8,%9}, {%0,%1,%2,%3};"               \
        : "+f"((c)[0]), "+f"((c)[1]), "+f"((c)[2]), "+f"((c)[3])              \
        : "r"(a0), "r"(a1), "r"(a2), "r"(a3), "r"(b0), "r"(b1))

__device__ __forceinline__ void cp_async16(uint32_t dst, const void* src, int valid) {
    asm volatile("cp.async.cg.shared.global [%0], [%1], 16, %2;"
                 :: "r"(dst), "l"(src), "r"(valid ? 16 : 0));
}

__global__ __launch_bounds__(256, 2)
void gemm_tf32_kernel(const float* __restrict__ x,
                      const float* __restrict__ bias,
                      float* __restrict__ out, int nrows) {
    extern __shared__ float sm[];
    float* xs = sm;                  // [2][4608] x double buffer
    float* ws = sm + 2 * XBUF;       // [4][4608] W tile, chunk layout (permuted k)

    const int tid = threadIdx.x;
    const int lane = tid & 31;
    const int wid = tid >> 5;
    const int g = lane >> 2;
    const int t4 = lane & 3;
    const int wm = wid >> 1;         // 0..3 (32 rows)
    const int wn = wid & 1;          // 0..1 (64 cols)
    const int row0 = blockIdx.x * TILE_M;

    const int lr = tid >> 3;         // 0..31
    const int lk = (tid & 7) << 2;   // 0,4,...,28

    const uint32_t xs_b = (uint32_t)__cvta_generic_to_shared(xs);
    const uint32_t ws_b = (uint32_t)__cvta_generic_to_shared(ws);

    // ---- W: one-time cp.async load (g_Wt image is already chunk/permute laid out)
#pragma unroll
    for (int it = 0; it < 16; it++) {
        int idx = tid + 256 * it;            // float4 index 0..4095
        int c = idx >> 10;
        int rem = idx & 1023;
        int n = rem >> 3, k4 = (rem & 7) << 2;
        cp_async16(ws_b + (uint32_t)(c * XBUF + n * CS + k4) * 4,
                   g_Wt + ((size_t)idx << 2), 1);
    }
    asm volatile("cp.async.commit_group;" ::: "memory");

    auto load_x_chunk = [&](int k0, int buf) {
        uint32_t xd = xs_b + (uint32_t)(buf * XBUF) * 4;
#pragma unroll
        for (int it = 0; it < 4; it++) {
            int r = lr + 32 * it;
            int grow = row0 + r;
            cp_async16(xd + (uint32_t)(r * CS + lk) * 4,
                       x + (size_t)grow * D + lk + k0, grow < nrows);
        }
        asm volatile("cp.async.commit_group;" ::: "memory");
    };

    load_x_chunk(0, 0);

    float acc[2][8][4];
#pragma unroll
    for (int i = 0; i < 2; i++)
#pragma unroll
        for (int j = 0; j < 8; j++)
#pragma unroll
            for (int p = 0; p < 4; p++) acc[i][j][p] = 0.0f;

    const float* xa_base = xs + (wm * 32 + g) * CS;              // + t4 applied below
    const float* wb_base = ws + (wn * 64 + g) * CS + 2 * t4;     // float2 lane base

#pragma unroll
    for (int c = 0; c < 4; c++) {
        asm volatile("cp.async.wait_group 0;" ::: "memory");
        __syncthreads();
        // prefetch next chunk AFTER the sync: safe with 2 buffers, single sync
        if (c < 3) load_x_chunk((c + 1) * KC, (c + 1) & 1);

        const float* xa = xa_base + (c & 1) * XBUF + t4;
        const float* wb = wb_base + c * XBUF;

#pragma unroll
        for (int s = 0; s < 4; s++) {
            const int k8 = 8 * s;
            uint32_t a[2][4];
#pragma unroll
            for (int i = 0; i < 2; i++) {
                a[i][0] = __float_as_uint(xa[(16 * i) * CS + k8]);
                a[i][1] = __float_as_uint(xa[(16 * i + 8) * CS + k8]);
                a[i][2] = __float_as_uint(xa[(16 * i) * CS + k8 + 4]);
                a[i][3] = __float_as_uint(xa[(16 * i + 8) * CS + k8 + 4]);
            }
            uint32_t b[8][2];
#pragma unroll
            for (int j = 0; j < 8; j++) {
                float2 v = *(const float2*)(wb + j * 8 * CS + k8);
                b[j][0] = __float_as_uint(v.x);
                b[j][1] = __float_as_uint(v.y);
            }
#pragma unroll
            for (int i = 0; i < 2; i++)
#pragma unroll
                for (int j = 0; j < 8; j++)
                    MMA_TF32(acc[i][j], a[i][0], a[i][1], a[i][2], a[i][3],
                             b[j][0], b[j][1]);
        }
    }

    // ---- epilogue: bias + store directly from accumulators ----
#pragma unroll
    for (int j = 0; j < 8; j++) {
        int col = wn * 64 + 8 * j + 2 * t4;
        float b0 = __ldg(bias + col), b1 = __ldg(bias + col + 1);
#pragma unroll
        for (int i = 0; i < 2; i++) {
            int r_lo = row0 + wm * 32 + 16 * i + g;
            int r_hi = r_lo + 8;
            if (r_lo < nrows) {
                float2 v = make_float2(acc[i][j][0] + b0, acc[i][j][1] + b1);
                *(float2*)(out + (size_t)r_lo * D + col) = v;
            }
            if (r_hi < nrows) {
                float2 v = make_float2(acc[i][j][2] + b0, acc[i][j][3] + b1);
                *(float2*)(out + (size_t)r_hi * D + col) = v;
            }
        }
    }
}

extern "C" void kernel_launch(void* const* d_in, const int* in_sizes, int n_in,
                              void* d_out, int out_size) {
    const float* x    = (const float*)d_in[0];
    const float* Wc   = (const float*)d_in[2];
    const float* Wn   = (const float*)d_in[3];
    const float* bias = (const float*)d_in[4];
    float* out = (float*)d_out;

    const int nrows = in_sizes[0] / D;                 // 100000

    prep_w_kernel<<<(D * D + 255) / 256, 256>>>(Wc, Wn);

    const int smem_bytes = 6 * XBUF * 4;               // 110,592 B
    cudaFuncSetAttribute(gemm_tf32_kernel,
                         cudaFuncAttributeMaxDynamicSharedMemorySize, smem_bytes);

    int grid = (nrows + TILE_M - 1) / TILE_M;          // 782
    gemm_tf32_kernel<<<grid, 256, smem_bytes>>>(x, bias, out, nrows);
}

// round 8
// speedup vs baseline: 1.3098x; 1.2669x over previous
#include <cuda_runtime.h>
#include <cstdint>

// out[100000,128] = x[100000,128] @ (Wc+Wn)[128,128] + b[128]
// (gamma/segment-sum in the reference is dead code; edge_index unused)
//
// tf32 mma.sync (m16n8k8). CTA 128x128, 8 warps of 32x64, 2 CTAs/SM.
// W pre-swizzled into MMA-fragment order (unit-stride LDS.64, conflict-free).
// x streamed in K=32 cp.async chunks, single sync/chunk, interleaved prologue.
//
// Inputs: d_in[0]=x f32 [100000,128], d_in[1]=edge_index i64 (UNUSED),
//         d_in[2]=Wc f32 [128,128], d_in[3]=Wn f32 [128,128], d_in[4]=b f32 [128]

#define D 128
#define TILE_M 128
#define KC 32
#define CS 36                    // x row stride (floats): conflict-free LDS.32
#define XBUF (TILE_M * CS)       // 4608 floats per x buffer
#define WCH 4096                 // W floats per chunk (128n x 32k), frag-ordered

// W fragment image: idx = ((((c*2+wn)*4+s)*8+j)*32+lane)*2+h
//   n = wn*64 + j*8 + (lane>>2), k = c*32 + s*8 + (lane&3) + 4*h
__device__ float g_Wt[D * D];

__device__ __forceinline__ float to_tf32(float f) {
    float r;
    asm("cvt.rna.tf32.f32 %0, %1;" : "=f"(r) : "f"(f));
    return r;
}

__global__ void prep_w_kernel(const float* __restrict__ Wc,
                              const float* __restrict__ Wn) {
    int i = blockIdx.x * blockDim.x + threadIdx.x;
    if (i >= D * D) return;
    int h = i & 1, lane = (i >> 1) & 31, j = (i >> 6) & 7;
    int s = (i >> 9) & 3, wn = (i >> 11) & 1, c = i >> 12;
    int n = wn * 64 + j * 8 + (lane >> 2);
    int k = c * 32 + s * 8 + (lane & 3) + 4 * h;
    g_Wt[i] = to_tf32(Wc[k * D + n] + Wn[k * D + n]);
}

#define MMA_TF32(c, a0, a1, a2, a3, b0, b1)                                   \
    asm volatile(                                                             \
        "mma.sync.aligned.m16n8k8.row.col.f32.tf32.tf32.f32 "                 \
        "{%0,%1,%2,%3}, {%4,%5,%6,%7}, {%8,%9}, {%0,%1,%2,%3};"               \
        : "+f"((c)[0]), "+f"((c)[1]), "+f"((c)[2]), "+f"((c)[3])              \
        : "r"(a0), "r"(a1), "r"(a2), "r"(a3), "r"(b0), "r"(b1))

__device__ __forceinline__ void cp_async16(uint32_t dst, const void* src, int valid) {
    asm volatile("cp.async.cg.shared.global [%0], [%1], 16, %2;"
                 :: "r"(dst), "l"(src), "r"(valid ? 16 : 0));
}

__global__ __launch_bounds__(256, 2)
void gemm_tf32_kernel(const float* __restrict__ x,
                      const float* __restrict__ bias,
                      float* __restrict__ out, int nrows) {
    extern __shared__ float sm[];
    float* xs = sm;                  // [2][4608]
    float* ws = sm + 2 * XBUF;       // [4][4096] frag-ordered W

    const int tid = threadIdx.x;
    const int lane = tid & 31;
    const int wid = tid >> 5;
    const int g = lane >> 2;
    const int t4 = lane & 3;
    const int wm = wid >> 1;         // 0..3
    const int wn = wid & 1;          // 0..1
    const int row0 = blockIdx.x * TILE_M;

    const int lr = tid >> 3;
    const int lk = (tid & 7) << 2;

    const uint32_t xs_b = (uint32_t)__cvta_generic_to_shared(xs);
    const uint32_t ws_b = (uint32_t)__cvta_generic_to_shared(ws);

    auto load_x_chunk = [&](int k0, int buf) {
        uint32_t xd = xs_b + (uint32_t)(buf * XBUF) * 4;
#pragma unroll
        for (int it = 0; it < 4; it++) {
            int r = lr + 32 * it;
            int grow = row0 + r;
            cp_async16(xd + (uint32_t)(r * CS + lk) * 4,
                       x + (size_t)grow * D + lk + k0, grow < nrows);
        }
        asm volatile("cp.async.commit_group;" ::: "memory");
    };

    // ---- prologue: Wc0 | x0 | Wc1-3 (three groups, in that order) ----
#pragma unroll
    for (int it = 0; it < 4; it++) {  // W chunk 0: 1024 float4s
        int idx = tid + 256 * it;
        cp_async16(ws_b + (uint32_t)idx * 16, g_Wt + ((size_t)idx << 2), 1);
    }
    asm volatile("cp.async.commit_group;" ::: "memory");

    load_x_chunk(0, 0);

#pragma unroll
    for (int it = 0; it < 12; it++) {  // W chunks 1-3: 3072 float4s
        int idx = 1024 + tid + 256 * it;
        cp_async16(ws_b + (uint32_t)idx * 16, g_Wt + ((size_t)idx << 2), 1);
    }
    asm volatile("cp.async.commit_group;" ::: "memory");

    float acc[2][8][4];
#pragma unroll
    for (int i = 0; i < 2; i++)
#pragma unroll
        for (int j = 0; j < 8; j++)
#pragma unroll
            for (int p = 0; p < 4; p++) acc[i][j][p] = 0.0f;

    const float* xa_base = xs + (wm * 32 + g) * CS + t4;
    const float* wb_base = ws + wn * 2048 + lane * 2;

#pragma unroll
    for (int c = 0; c < 4; c++) {
        if (c == 0)
            asm volatile("cp.async.wait_group 1;" ::: "memory");  // Wc0 + x0
        else
            asm volatile("cp.async.wait_group 0;" ::: "memory");
        __syncthreads();
        if (c < 3) load_x_chunk((c + 1) * KC, (c + 1) & 1);  // after sync: safe

        const float* xa = xa_base + (c & 1) * XBUF;
        const float* wb = wb_base + c * WCH;

#pragma unroll
        for (int s = 0; s < 4; s++) {
            const int k8 = 8 * s;
            uint32_t a[2][4];
#pragma unroll
            for (int i = 0; i < 2; i++) {
                a[i][0] = __float_as_uint(xa[(16 * i) * CS + k8]);
                a[i][1] = __float_as_uint(xa[(16 * i + 8) * CS + k8]);
                a[i][2] = __float_as_uint(xa[(16 * i) * CS + k8 + 4]);
                a[i][3] = __float_as_uint(xa[(16 * i + 8) * CS + k8 + 4]);
            }
            uint32_t b[8][2];
#pragma unroll
            for (int j = 0; j < 8; j++) {
                float2 v = *(const float2*)(wb + s * 512 + j * 64);
                b[j][0] = __float_as_uint(v.x);
                b[j][1] = __float_as_uint(v.y);
            }
#pragma unroll
            for (int i = 0; i < 2; i++)
#pragma unroll
                for (int j = 0; j < 8; j++)
                    MMA_TF32(acc[i][j], a[i][0], a[i][1], a[i][2], a[i][3],
                             b[j][0], b[j][1]);
        }
    }

    // ---- epilogue: bias + store directly from accumulators ----
#pragma unroll
    for (int j = 0; j < 8; j++) {
        int col = wn * 64 + 8 * j + 2 * t4;
        float b0 = __ldg(bias + col), b1 = __ldg(bias + col + 1);
#pragma unroll
        for (int i = 0; i < 2; i++) {
            int r_lo = row0 + wm * 32 + 16 * i + g;
            int r_hi = r_lo + 8;
            if (r_lo < nrows) {
                float2 v = make_float2(acc[i][j][0] + b0, acc[i][j][1] + b1);
                *(float2*)(out + (size_t)r_lo * D + col) = v;
            }
            if (r_hi < nrows) {
                float2 v = make_float2(acc[i][j][2] + b0, acc[i][j][3] + b1);
                *(float2*)(out + (size_t)r_hi * D + col) = v;
            }
        }
    }
}

extern "C" void kernel_launch(void* const* d_in, const int* in_sizes, int n_in,
                              void* d_out, int out_size) {
    const float* x    = (const float*)d_in[0];
    const float* Wc   = (const float*)d_in[2];
    const float* Wn   = (const float*)d_in[3];
    const float* bias = (const float*)d_in[4];
    float* out = (float*)d_out;

    const int nrows = in_sizes[0] / D;                 // 100000

    prep_w_kernel<<<(D * D + 255) / 256, 256>>>(Wc, Wn);

    const int smem_bytes = (2 * XBUF + 4 * WCH) * 4;   // 102,400 B
    cudaFuncSetAttribute(gemm_tf32_kernel,
                         cudaFuncAttributeMaxDynamicSharedMemorySize, smem_bytes);

    int grid = (nrows + TILE_M - 1) / TILE_M;          // 782
    gemm_tf32_kernel<<<grid, 256, smem_bytes>>>(x, bias, out, nrows);
}